// round 11
// baseline (speedup 1.0000x reference)
#include <cuda_runtime.h>
#include <cuda_bf16.h>

// SumGoalHistory: out_t = sigmoid(init + prefix_sum(goal, axis=T)), final x2.
// goal [512, 64, 1024] fp32. One thread per 2 columns (float2), all T=512
// timesteps per column. Rotating register buffer NB=64 (consume-then-refill,
// prefetch distance 64) -> ~16.8 MB in flight chip-wide (DRAM-saturating).
// 64-thread CTAs / 512 blocks: the geometry with the lowest measured
// bench-vs-kernel overhead.

#define T_DIM 512
#define BD    (64 * 1024)
#define NCOL2 (BD / 2)     // 32768 float2 columns
#define NB    64

__device__ __forceinline__ float fast_sigmoid(float x) {
    float t;
    asm("tanh.approx.f32 %0, %1;" : "=f"(t) : "f"(0.5f * x));
    return fmaf(0.5f, t, 0.5f);
}

__global__ __launch_bounds__(64)
void SumGoalHistory_19387482374813_kernel(const float2* __restrict__ goal,
                                          const float2* __restrict__ init_state,
                                          float2* __restrict__ out) {
    const int col = blockIdx.x * blockDim.x + threadIdx.x;  // 0 .. NCOL2-1

    float2 acc = init_state[col];
    const float2* g = goal + col;
    float2*       o = out  + col;

    float2 buf[NB];
    // Prologue: 64 independent LDG.64 in flight (timesteps 0..63).
    #pragma unroll
    for (int u = 0; u < NB; u++)
        buf[u] = __ldcs(g + (size_t)u * NCOL2);

    // Main loop: t0 = 0, 64, ..., 384 (7 iterations).
    // Consume timestep t0+u, refill with timestep t0+NB+u.
    for (int t0 = 0; t0 < T_DIM - NB; t0 += NB) {
        #pragma unroll
        for (int u = 0; u < NB; u++) {
            float2 v = buf[u];
            buf[u] = __ldcs(g + (size_t)(t0 + NB + u) * NCOL2);
            acc.x += v.x;
            acc.y += v.y;
            float2 s = make_float2(fast_sigmoid(acc.x), fast_sigmoid(acc.y));
            __stcs(o + (size_t)(t0 + u) * NCOL2, s);
        }
    }

    // Epilogue: timesteps 448..511, no refill.
    #pragma unroll
    for (int u = 0; u < NB; u++) {
        acc.x += buf[u].x;
        acc.y += buf[u].y;
        float2 s = make_float2(fast_sigmoid(acc.x), fast_sigmoid(acc.y));
        __stcs(o + (size_t)(T_DIM - NB + u) * NCOL2, s);
    }

    // final_state written twice after the outputs block
    __stcs(o + (size_t)T_DIM * NCOL2,       acc);
    __stcs(o + (size_t)(T_DIM + 1) * NCOL2, acc);
}

extern "C" void kernel_launch(void* const* d_in, const int* in_sizes, int n_in,
                              void* d_out, int out_size) {
    const float2* goal = (const float2*)d_in[0];
    const float2* init = (const float2*)d_in[1];
    float2* out = (float2*)d_out;

    SumGoalHistory_19387482374813_kernel<<<NCOL2 / 64, 64>>>(goal, init, out);
}

// round 12
// speedup vs baseline: 1.0878x; 1.0878x over previous
#include <cuda_runtime.h>
#include <cuda_bf16.h>

// SumGoalHistory: out_t = sigmoid(init + prefix_sum(goal, axis=T)), final x2.
// goal [512, 64, 1024] fp32. One thread per 2 columns (float2), rotating
// register buffer NB=32 (consume-then-refill, prefetch distance 32) -> 8.4 MB
// in flight chip-wide. 64-thread CTAs / 512 blocks.
// This is the measured bench optimum: larger NB (64) gains ~1.5us in isolated
// ncu captures but loses 3-5us in the sustained timed loop (power/overhead),
// and DRAM% saturates at ~69% regardless (mixed R/W stream ceiling).

#define T_DIM 512
#define BD    (64 * 1024)
#define NCOL2 (BD / 2)     // 32768 float2 columns
#define NB    32

__device__ __forceinline__ float fast_sigmoid(float x) {
    float t;
    asm("tanh.approx.f32 %0, %1;" : "=f"(t) : "f"(0.5f * x));
    return fmaf(0.5f, t, 0.5f);
}

__global__ __launch_bounds__(64)
void SumGoalHistory_19387482374813_kernel(const float2* __restrict__ goal,
                                          const float2* __restrict__ init_state,
                                          float2* __restrict__ out) {
    const int col = blockIdx.x * blockDim.x + threadIdx.x;  // 0 .. NCOL2-1

    float2 acc = init_state[col];
    const float2* g = goal + col;
    float2*       o = out  + col;

    float2 buf[NB];
    // Prologue: 32 independent LDG.64 in flight (timesteps 0..31).
    #pragma unroll
    for (int u = 0; u < NB; u++)
        buf[u] = __ldcs(g + (size_t)u * NCOL2);

    // Main loop: t0 = 0, 32, ..., 448 (15 iterations).
    // Consume timestep t0+u, refill with timestep t0+NB+u.
    for (int t0 = 0; t0 < T_DIM - NB; t0 += NB) {
        #pragma unroll
        for (int u = 0; u < NB; u++) {
            float2 v = buf[u];
            buf[u] = __ldcs(g + (size_t)(t0 + NB + u) * NCOL2);
            acc.x += v.x;
            acc.y += v.y;
            float2 s = make_float2(fast_sigmoid(acc.x), fast_sigmoid(acc.y));
            __stcs(o + (size_t)(t0 + u) * NCOL2, s);
        }
    }

    // Epilogue: timesteps 480..511, no refill.
    #pragma unroll
    for (int u = 0; u < NB; u++) {
        acc.x += buf[u].x;
        acc.y += buf[u].y;
        float2 s = make_float2(fast_sigmoid(acc.x), fast_sigmoid(acc.y));
        __stcs(o + (size_t)(T_DIM - NB + u) * NCOL2, s);
    }

    // final_state written twice after the outputs block
    __stcs(o + (size_t)T_DIM * NCOL2,       acc);
    __stcs(o + (size_t)(T_DIM + 1) * NCOL2, acc);
}

extern "C" void kernel_launch(void* const* d_in, const int* in_sizes, int n_in,
                              void* d_out, int out_size) {
    const float2* goal = (const float2*)d_in[0];
    const float2* init = (const float2*)d_in[1];
    float2* out = (float2*)d_out;

    SumGoalHistory_19387482374813_kernel<<<NCOL2 / 64, 64>>>(goal, init, out);
}